// round 5
// baseline (speedup 1.0000x reference)
#include <cuda_runtime.h>

// UniSAGE is fully linear => pull the final averaging functionals backwards.
// Only scalar/float2 per-vertex & per-edge vectors are materialized.
// R5: 8 elements/thread in NNZ passes (two int4 index loads, 8 front-batched
// gathers, 8 reds) to raise memory-level parallelism; vectorized prep.

#define NV   100000
#define NE   200000
#define NNZt 800000
#define DIN  14
#define HID  128
#define WP   (1.0f / (float)NV)
#define WR   (1.0f / (float)NE)

// NNZ pass geometry: 8 elems/thread. 800000/8 = 100000 threads exactly.
#define NNZ_BLK   256
#define NNZ_GRID  ((NNZt / 8 + NNZ_BLK - 1) / NNZ_BLK)   // 391
#define NNZ_THREADS (NNZt / 8)                            // 100000

// -------- device scratch (allocation-free), one block for a single memset ----
struct Scratch {
    float  deg[NV];
    float2 pv2[NV];    // {p_raw, r2_raw}
    float  p2 [NV];    // p2_raw
    float2 ze [NE];    // {zp, edeg}
    float  zp2[NE];
    float  acc[32];    // [0..13]=p2^T X, [14..27]=r2^T X, 28=Σp, 29=Σp2, 30=Σr2
    unsigned int tick;
};
__device__ Scratch g_s;
__device__ float g_q[NV];      // (p_raw + 1/NV)/deg  (written before read)

__device__ __forceinline__ void red2(float2* a, float x, float y) {
    asm volatile("red.global.add.v2.f32 [%0], {%1,%2};" :: "l"(a), "f"(x), "f"(y) : "memory");
}
__device__ __forceinline__ void red1(float* a, float x) {
    asm volatile("red.global.add.f32 [%0], %1;" :: "l"(a), "f"(x) : "memory");
}

__global__ void __launch_bounds__(NNZ_BLK) k_deg(const int* __restrict__ rows) {
    int t = blockIdx.x * NNZ_BLK + threadIdx.x;
    if (t >= NNZ_THREADS) return;
    const int4* r4 = (const int4*)(rows) + t * 2;
    int4 r0 = r4[0], r1 = r4[1];
    red1(&g_s.deg[r0.x], 1.f); red1(&g_s.deg[r0.y], 1.f);
    red1(&g_s.deg[r0.z], 1.f); red1(&g_s.deg[r0.w], 1.f);
    red1(&g_s.deg[r1.x], 1.f); red1(&g_s.deg[r1.y], 1.f);
    red1(&g_s.deg[r1.z], 1.f); red1(&g_s.deg[r1.w], 1.f);
}

// ze[e] += { (1/NV)/deg[v], 1 }   (zp scatter + edge-degree count fused)
__global__ void __launch_bounds__(NNZ_BLK) k_scat1(const int* __restrict__ rows,
                                                   const int* __restrict__ cols) {
    int t = blockIdx.x * NNZ_BLK + threadIdx.x;
    if (t >= NNZ_THREADS) return;
    const int4* r4 = (const int4*)(rows) + t * 2;
    const int4* c4 = (const int4*)(cols) + t * 2;
    int4 r0 = r4[0], r1 = r4[1];
    int4 c0 = c4[0], c1 = c4[1];
    // 8 independent gathers (front-batched), then 8 reds
    float d0 = g_s.deg[r0.x], d1 = g_s.deg[r0.y], d2 = g_s.deg[r0.z], d3 = g_s.deg[r0.w];
    float d4 = g_s.deg[r1.x], d5 = g_s.deg[r1.y], d6 = g_s.deg[r1.z], d7 = g_s.deg[r1.w];
    red2(&g_s.ze[c0.x], __fdividef(WP, d0), 1.f);
    red2(&g_s.ze[c0.y], __fdividef(WP, d1), 1.f);
    red2(&g_s.ze[c0.z], __fdividef(WP, d2), 1.f);
    red2(&g_s.ze[c0.w], __fdividef(WP, d3), 1.f);
    red2(&g_s.ze[c1.x], __fdividef(WP, d4), 1.f);
    red2(&g_s.ze[c1.y], __fdividef(WP, d5), 1.f);
    red2(&g_s.ze[c1.z], __fdividef(WP, d6), 1.f);
    red2(&g_s.ze[c1.w], __fdividef(WP, d7), 1.f);
}

// pv2[v] += { zp[e], edeg[e]/NE }
__global__ void __launch_bounds__(NNZ_BLK) k_gath1(const int* __restrict__ rows,
                                                   const int* __restrict__ cols) {
    int t = blockIdx.x * NNZ_BLK + threadIdx.x;
    if (t >= NNZ_THREADS) return;
    const int4* r4 = (const int4*)(rows) + t * 2;
    const int4* c4 = (const int4*)(cols) + t * 2;
    int4 r0 = r4[0], r1 = r4[1];
    int4 c0 = c4[0], c1 = c4[1];
    float2 z0 = g_s.ze[c0.x], z1 = g_s.ze[c0.y], z2 = g_s.ze[c0.z], z3 = g_s.ze[c0.w];
    float2 z4 = g_s.ze[c1.x], z5 = g_s.ze[c1.y], z6 = g_s.ze[c1.z], z7 = g_s.ze[c1.w];
    red2(&g_s.pv2[r0.x], z0.x, z0.y * WR);
    red2(&g_s.pv2[r0.y], z1.x, z1.y * WR);
    red2(&g_s.pv2[r0.z], z2.x, z2.y * WR);
    red2(&g_s.pv2[r0.w], z3.x, z3.y * WR);
    red2(&g_s.pv2[r1.x], z4.x, z4.y * WR);
    red2(&g_s.pv2[r1.y], z5.x, z5.y * WR);
    red2(&g_s.pv2[r1.z], z6.x, z6.y * WR);
    red2(&g_s.pv2[r1.w], z7.x, z7.y * WR);
}

// q[v] = (p_raw[v] + 1/NV) / deg[v], 4 vertices/thread vectorized
__global__ void k_prep() {
    int t = blockIdx.x * blockDim.x + threadIdx.x;
    int v = t * 4;
    if (v + 3 < NV) {
        float4 d  = *(const float4*)&g_s.deg[v];
        float4 pa = *(const float4*)&g_s.pv2[v];     // pv2[v].x, .y, pv2[v+1].x, .y
        float4 pb = *(const float4*)&g_s.pv2[v + 2];
        float4 q;
        q.x = __fdividef(pa.x + WP, d.x > 0.f ? d.x : 1.f);
        q.y = __fdividef(pa.z + WP, d.y > 0.f ? d.y : 1.f);
        q.z = __fdividef(pb.x + WP, d.z > 0.f ? d.z : 1.f);
        q.w = __fdividef(pb.z + WP, d.w > 0.f ? d.w : 1.f);
        *(float4*)&g_q[v] = q;
    } else {
        for (; v < NV; v++) {
            float dd = g_s.deg[v];
            g_q[v] = __fdividef(g_s.pv2[v].x + WP, dd > 0.f ? dd : 1.f);
        }
    }
}

__global__ void __launch_bounds__(NNZ_BLK) k_scat2(const int* __restrict__ rows,
                                                   const int* __restrict__ cols) {
    int t = blockIdx.x * NNZ_BLK + threadIdx.x;
    if (t >= NNZ_THREADS) return;
    const int4* r4 = (const int4*)(rows) + t * 2;
    const int4* c4 = (const int4*)(cols) + t * 2;
    int4 r0 = r4[0], r1 = r4[1];
    int4 c0 = c4[0], c1 = c4[1];
    float q0 = g_q[r0.x], q1 = g_q[r0.y], q2 = g_q[r0.z], q3 = g_q[r0.w];
    float q4 = g_q[r1.x], q5 = g_q[r1.y], q6 = g_q[r1.z], q7 = g_q[r1.w];
    red1(&g_s.zp2[c0.x], q0); red1(&g_s.zp2[c0.y], q1);
    red1(&g_s.zp2[c0.z], q2); red1(&g_s.zp2[c0.w], q3);
    red1(&g_s.zp2[c1.x], q4); red1(&g_s.zp2[c1.y], q5);
    red1(&g_s.zp2[c1.z], q6); red1(&g_s.zp2[c1.w], q7);
}

__global__ void __launch_bounds__(NNZ_BLK) k_gath2(const int* __restrict__ rows,
                                                   const int* __restrict__ cols) {
    int t = blockIdx.x * NNZ_BLK + threadIdx.x;
    if (t >= NNZ_THREADS) return;
    const int4* r4 = (const int4*)(rows) + t * 2;
    const int4* c4 = (const int4*)(cols) + t * 2;
    int4 r0 = r4[0], r1 = r4[1];
    int4 c0 = c4[0], c1 = c4[1];
    float z0 = g_s.zp2[c0.x], z1 = g_s.zp2[c0.y], z2 = g_s.zp2[c0.z], z3 = g_s.zp2[c0.w];
    float z4 = g_s.zp2[c1.x], z5 = g_s.zp2[c1.y], z6 = g_s.zp2[c1.z], z7 = g_s.zp2[c1.w];
    red1(&g_s.p2[r0.x], z0); red1(&g_s.p2[r0.y], z1);
    red1(&g_s.p2[r0.z], z2); red1(&g_s.p2[r0.w], z3);
    red1(&g_s.p2[r1.x], z4); red1(&g_s.p2[r1.y], z5);
    red1(&g_s.p2[r1.z], z6); red1(&g_s.p2[r1.w], z7);
}

// per-vertex reduction (Σp, Σp2, Σr2, p2^T X, r2^T X) + fused final GEMV chain
// in the last-finishing block (ticket pattern).
__global__ void k_reduce_final(const float* __restrict__ x0,
                               const float* __restrict__ W0, const float* __restrict__ b0,
                               const float* __restrict__ Wl0, const float* __restrict__ bl0,
                               const float* __restrict__ Wl1, const float* __restrict__ bl1,
                               const float* __restrict__ Wo0, const float* __restrict__ bo0,
                               const float* __restrict__ Wo1, const float* __restrict__ bo1,
                               float* __restrict__ out) {
    int v = blockIdx.x * blockDim.x + threadIdx.x;
    float vals[31];
#pragma unroll
    for (int k = 0; k < 31; k++) vals[k] = 0.f;
    if (v < NV) {
        float2 pr = g_s.pv2[v];
        float pv  = pr.x + WP;                    // full p (identity folded)
        float p2v = g_s.p2[v] + pv;               // p2 = p2_raw + p
        float r2v = pr.y + g_s.deg[v] * WR;       // r2 = r2_raw + r
        const float* xr = x0 + (long long)v * DIN;
#pragma unroll
        for (int j = 0; j < DIN; j++) {
            float x = xr[j];
            vals[j]      = p2v * x;
            vals[14 + j] = r2v * x;
        }
        vals[28] = pv; vals[29] = p2v; vals[30] = r2v;
    }
#pragma unroll
    for (int k = 0; k < 31; k++) {
#pragma unroll
        for (int off = 16; off > 0; off >>= 1)
            vals[k] += __shfl_down_sync(0xffffffffu, vals[k], off);
    }
    __shared__ float sh[8 * 31];
    int warp = threadIdx.x >> 5, lane = threadIdx.x & 31;
    if (lane == 0) {
#pragma unroll
        for (int k = 0; k < 31; k++) sh[warp * 31 + k] = vals[k];
    }
    __syncthreads();
    if (threadIdx.x < 31) {
        float s = 0.f;
#pragma unroll
        for (int w = 0; w < 8; w++) s += sh[w * 31 + threadIdx.x];
        atomicAdd(&g_s.acc[threadIdx.x], s);
    }

    // ---- ticket: last block to finish runs the tiny GEMV chain ----
    __threadfence();
    __shared__ unsigned int is_last;
    if (threadIdx.x == 0)
        is_last = (atomicInc(&g_s.tick, gridDim.x - 1) == gridDim.x - 1) ? 1u : 0u;
    __syncthreads();
    if (!is_last) return;
    __threadfence();

    __shared__ float a0[HID], c0[HID], a1[HID], c1[HID], red[HID];
    int h = threadIdx.x;
    float sp  = g_s.acc[28];
    float sp2 = g_s.acc[29];
    float sr2 = g_s.acc[30];
    float sr  = (float)NNZt / (float)NE;

    if (h < HID) {
        float sa = 0.f, sc = 0.f;
#pragma unroll
        for (int j = 0; j < DIN; j++) {
            float w = W0[j * HID + h];
            sa += g_s.acc[j] * w;
            sc += g_s.acc[14 + j] * w;
        }
        a0[h] = sa + sp2 * b0[h];
        c0[h] = sc + sr2 * b0[h];
    }
    __syncthreads();
    if (h < HID) {
        float sa = 0.f, sc = 0.f;
        for (int m = 0; m < HID; m++) {
            float w = Wl0[m * HID + h];
            sa += a0[m] * w;
            sc += c0[m] * w;
        }
        a1[h] = sa + sp2 * bl0[h];
        c1[h] = sc + sr2 * bl0[h];
    }
    __syncthreads();
    if (h < HID) {
        float sa = 0.f, sc = 0.f;
        for (int m = 0; m < HID; m++) {
            float w = Wl1[m * HID + h];
            sa += a1[m] * w;
            sc += c1[m] * w;
        }
        float a2h = sa + sp * bl1[h];
        float c2h = sc + sr * bl1[h];
        red[h] = a2h * Wo0[h] + c2h * Wo1[h];
    }
    __syncthreads();
    for (int s = HID / 2; s > 0; s >>= 1) {
        if (h < s) red[h] += red[h + s];
        __syncthreads();
    }
    if (h == 0) out[0] = red[0] + bo0[0] + bo1[0];
}

extern "C" void kernel_launch(void* const* d_in, const int* in_sizes, int n_in,
                              void* d_out, int out_size) {
    const float* x_0  = (const float*)d_in[0];
    const int*   rows = (const int*)d_in[2];
    const int*   cols = (const int*)d_in[3];
    const float* W0   = (const float*)d_in[4];
    const float* b0   = (const float*)d_in[5];
    const float* Wl0  = (const float*)d_in[8];
    const float* bl0  = (const float*)d_in[9];
    const float* Wl1  = (const float*)d_in[10];
    const float* bl1  = (const float*)d_in[11];
    const float* Wo0  = (const float*)d_in[12];
    const float* bo0  = (const float*)d_in[13];
    const float* Wo1  = (const float*)d_in[14];
    const float* bo1  = (const float*)d_in[15];
    float* out = (float*)d_out;

    void* p_s;
    cudaGetSymbolAddress(&p_s, g_s);
    cudaMemsetAsync(p_s, 0, sizeof(Scratch));

    const int T = 256;
    const int gNV   = (NV + T - 1) / T;                 // 391
    const int gPrep = (NV / 4 + T - 1) / T;             // 98

    k_deg  <<<NNZ_GRID, NNZ_BLK>>>(rows);
    k_scat1<<<NNZ_GRID, NNZ_BLK>>>(rows, cols);
    k_gath1<<<NNZ_GRID, NNZ_BLK>>>(rows, cols);
    k_prep <<<gPrep, T>>>();
    k_scat2<<<NNZ_GRID, NNZ_BLK>>>(rows, cols);
    k_gath2<<<NNZ_GRID, NNZ_BLK>>>(rows, cols);
    k_reduce_final<<<gNV, T>>>(x_0, W0, b0, Wl0, bl0, Wl1, bl1,
                               Wo0, bo0, Wo1, bo1, out);
}

// round 6
// speedup vs baseline: 1.0006x; 1.0006x over previous
#include <cuda_runtime.h>

// UniSAGE is fully linear => pull the final averaging functionals backwards.
// Only scalar/float2 per-vertex & per-edge vectors are materialized.
// R6: NNZ passes are at the LSU random-op floor (9 ops/incidence, ~48us);
// fix the latency-bound vertex passes: prep at full grid (1 v/thread),
// reduce at 2 vertices/thread to halve shuffle overhead.

#define NV   100000
#define NE   200000
#define NNZt 800000
#define DIN  14
#define HID  128
#define WP   (1.0f / (float)NV)
#define WR   (1.0f / (float)NE)

// NNZ pass geometry: 8 elems/thread. 800000/8 = 100000 threads exactly.
#define NNZ_BLK   256
#define NNZ_GRID  ((NNZt / 8 + NNZ_BLK - 1) / NNZ_BLK)   // 391
#define NNZ_THREADS (NNZt / 8)                            // 100000

// reduce geometry: 2 vertices/thread, strided
#define RED_BLK   256
#define RED_GRID  196                     // 196*256 = 50176 threads
#define RED_STRIDE (RED_BLK * RED_GRID)   // 50176

// -------- device scratch (allocation-free), one block for a single memset ----
struct Scratch {
    float  deg[NV];
    float2 pv2[NV];    // {p_raw, r2_raw}
    float  p2 [NV];    // p2_raw
    float2 ze [NE];    // {zp, edeg}
    float  zp2[NE];
    float  acc[32];    // [0..13]=p2^T X, [14..27]=r2^T X, 28=Σp, 29=Σp2, 30=Σr2
    unsigned int tick;
};
__device__ Scratch g_s;
__device__ float g_q[NV];      // (p_raw + 1/NV)/deg  (written before read)

__device__ __forceinline__ void red2(float2* a, float x, float y) {
    asm volatile("red.global.add.v2.f32 [%0], {%1,%2};" :: "l"(a), "f"(x), "f"(y) : "memory");
}
__device__ __forceinline__ void red1(float* a, float x) {
    asm volatile("red.global.add.f32 [%0], %1;" :: "l"(a), "f"(x) : "memory");
}

__global__ void __launch_bounds__(NNZ_BLK) k_deg(const int* __restrict__ rows) {
    int t = blockIdx.x * NNZ_BLK + threadIdx.x;
    if (t >= NNZ_THREADS) return;
    const int4* r4 = (const int4*)(rows) + t * 2;
    int4 r0 = r4[0], r1 = r4[1];
    red1(&g_s.deg[r0.x], 1.f); red1(&g_s.deg[r0.y], 1.f);
    red1(&g_s.deg[r0.z], 1.f); red1(&g_s.deg[r0.w], 1.f);
    red1(&g_s.deg[r1.x], 1.f); red1(&g_s.deg[r1.y], 1.f);
    red1(&g_s.deg[r1.z], 1.f); red1(&g_s.deg[r1.w], 1.f);
}

// ze[e] += { (1/NV)/deg[v], 1 }   (zp scatter + edge-degree count fused)
__global__ void __launch_bounds__(NNZ_BLK) k_scat1(const int* __restrict__ rows,
                                                   const int* __restrict__ cols) {
    int t = blockIdx.x * NNZ_BLK + threadIdx.x;
    if (t >= NNZ_THREADS) return;
    const int4* r4 = (const int4*)(rows) + t * 2;
    const int4* c4 = (const int4*)(cols) + t * 2;
    int4 r0 = r4[0], r1 = r4[1];
    int4 c0 = c4[0], c1 = c4[1];
    float d0 = g_s.deg[r0.x], d1 = g_s.deg[r0.y], d2 = g_s.deg[r0.z], d3 = g_s.deg[r0.w];
    float d4 = g_s.deg[r1.x], d5 = g_s.deg[r1.y], d6 = g_s.deg[r1.z], d7 = g_s.deg[r1.w];
    red2(&g_s.ze[c0.x], __fdividef(WP, d0), 1.f);
    red2(&g_s.ze[c0.y], __fdividef(WP, d1), 1.f);
    red2(&g_s.ze[c0.z], __fdividef(WP, d2), 1.f);
    red2(&g_s.ze[c0.w], __fdividef(WP, d3), 1.f);
    red2(&g_s.ze[c1.x], __fdividef(WP, d4), 1.f);
    red2(&g_s.ze[c1.y], __fdividef(WP, d5), 1.f);
    red2(&g_s.ze[c1.z], __fdividef(WP, d6), 1.f);
    red2(&g_s.ze[c1.w], __fdividef(WP, d7), 1.f);
}

// pv2[v] += { zp[e], edeg[e]/NE }
__global__ void __launch_bounds__(NNZ_BLK) k_gath1(const int* __restrict__ rows,
                                                   const int* __restrict__ cols) {
    int t = blockIdx.x * NNZ_BLK + threadIdx.x;
    if (t >= NNZ_THREADS) return;
    const int4* r4 = (const int4*)(rows) + t * 2;
    const int4* c4 = (const int4*)(cols) + t * 2;
    int4 r0 = r4[0], r1 = r4[1];
    int4 c0 = c4[0], c1 = c4[1];
    float2 z0 = g_s.ze[c0.x], z1 = g_s.ze[c0.y], z2 = g_s.ze[c0.z], z3 = g_s.ze[c0.w];
    float2 z4 = g_s.ze[c1.x], z5 = g_s.ze[c1.y], z6 = g_s.ze[c1.z], z7 = g_s.ze[c1.w];
    red2(&g_s.pv2[r0.x], z0.x, z0.y * WR);
    red2(&g_s.pv2[r0.y], z1.x, z1.y * WR);
    red2(&g_s.pv2[r0.z], z2.x, z2.y * WR);
    red2(&g_s.pv2[r0.w], z3.x, z3.y * WR);
    red2(&g_s.pv2[r1.x], z4.x, z4.y * WR);
    red2(&g_s.pv2[r1.y], z5.x, z5.y * WR);
    red2(&g_s.pv2[r1.z], z6.x, z6.y * WR);
    red2(&g_s.pv2[r1.w], z7.x, z7.y * WR);
}

// q[v] = (p_raw[v] + 1/NV) / deg[v], 1 vertex/thread, full grid
__global__ void k_prep() {
    int v = blockIdx.x * blockDim.x + threadIdx.x;
    if (v < NV) {
        float d = g_s.deg[v];
        g_q[v] = __fdividef(g_s.pv2[v].x + WP, d > 0.f ? d : 1.f);
    }
}

__global__ void __launch_bounds__(NNZ_BLK) k_scat2(const int* __restrict__ rows,
                                                   const int* __restrict__ cols) {
    int t = blockIdx.x * NNZ_BLK + threadIdx.x;
    if (t >= NNZ_THREADS) return;
    const int4* r4 = (const int4*)(rows) + t * 2;
    const int4* c4 = (const int4*)(cols) + t * 2;
    int4 r0 = r4[0], r1 = r4[1];
    int4 c0 = c4[0], c1 = c4[1];
    float q0 = g_q[r0.x], q1 = g_q[r0.y], q2 = g_q[r0.z], q3 = g_q[r0.w];
    float q4 = g_q[r1.x], q5 = g_q[r1.y], q6 = g_q[r1.z], q7 = g_q[r1.w];
    red1(&g_s.zp2[c0.x], q0); red1(&g_s.zp2[c0.y], q1);
    red1(&g_s.zp2[c0.z], q2); red1(&g_s.zp2[c0.w], q3);
    red1(&g_s.zp2[c1.x], q4); red1(&g_s.zp2[c1.y], q5);
    red1(&g_s.zp2[c1.z], q6); red1(&g_s.zp2[c1.w], q7);
}

__global__ void __launch_bounds__(NNZ_BLK) k_gath2(const int* __restrict__ rows,
                                                   const int* __restrict__ cols) {
    int t = blockIdx.x * NNZ_BLK + threadIdx.x;
    if (t >= NNZ_THREADS) return;
    const int4* r4 = (const int4*)(rows) + t * 2;
    const int4* c4 = (const int4*)(cols) + t * 2;
    int4 r0 = r4[0], r1 = r4[1];
    int4 c0 = c4[0], c1 = c4[1];
    float z0 = g_s.zp2[c0.x], z1 = g_s.zp2[c0.y], z2 = g_s.zp2[c0.z], z3 = g_s.zp2[c0.w];
    float z4 = g_s.zp2[c1.x], z5 = g_s.zp2[c1.y], z6 = g_s.zp2[c1.z], z7 = g_s.zp2[c1.w];
    red1(&g_s.p2[r0.x], z0); red1(&g_s.p2[r0.y], z1);
    red1(&g_s.p2[r0.z], z2); red1(&g_s.p2[r0.w], z3);
    red1(&g_s.p2[r1.x], z4); red1(&g_s.p2[r1.y], z5);
    red1(&g_s.p2[r1.z], z6); red1(&g_s.p2[r1.w], z7);
}

// per-vertex reduction (Σp, Σp2, Σr2, p2^T X, r2^T X), 2 vertices/thread,
// + fused final GEMV chain in the last-finishing block (ticket pattern).
__global__ void __launch_bounds__(RED_BLK)
k_reduce_final(const float* __restrict__ x0,
               const float* __restrict__ W0, const float* __restrict__ b0,
               const float* __restrict__ Wl0, const float* __restrict__ bl0,
               const float* __restrict__ Wl1, const float* __restrict__ bl1,
               const float* __restrict__ Wo0, const float* __restrict__ bo0,
               const float* __restrict__ Wo1, const float* __restrict__ bo1,
               float* __restrict__ out) {
    int t = blockIdx.x * RED_BLK + threadIdx.x;
    float vals[31];
#pragma unroll
    for (int k = 0; k < 31; k++) vals[k] = 0.f;

#pragma unroll
    for (int rep = 0; rep < 2; rep++) {
        int v = t + rep * RED_STRIDE;
        if (v < NV) {
            float2 pr = g_s.pv2[v];
            float pv  = pr.x + WP;                    // full p (identity folded)
            float p2v = g_s.p2[v] + pv;               // p2 = p2_raw + p
            float r2v = pr.y + g_s.deg[v] * WR;       // r2 = r2_raw + r
            const float* xr = x0 + (long long)v * DIN;
#pragma unroll
            for (int j = 0; j < DIN; j++) {
                float x = xr[j];
                vals[j]      += p2v * x;
                vals[14 + j] += r2v * x;
            }
            vals[28] += pv; vals[29] += p2v; vals[30] += r2v;
        }
    }
#pragma unroll
    for (int k = 0; k < 31; k++) {
#pragma unroll
        for (int off = 16; off > 0; off >>= 1)
            vals[k] += __shfl_down_sync(0xffffffffu, vals[k], off);
    }
    __shared__ float sh[8 * 31];
    int warp = threadIdx.x >> 5, lane = threadIdx.x & 31;
    if (lane == 0) {
#pragma unroll
        for (int k = 0; k < 31; k++) sh[warp * 31 + k] = vals[k];
    }
    __syncthreads();
    if (threadIdx.x < 31) {
        float s = 0.f;
#pragma unroll
        for (int w = 0; w < 8; w++) s += sh[w * 31 + threadIdx.x];
        atomicAdd(&g_s.acc[threadIdx.x], s);
    }

    // ---- ticket: last block to finish runs the tiny GEMV chain ----
    __threadfence();
    __shared__ unsigned int is_last;
    if (threadIdx.x == 0)
        is_last = (atomicInc(&g_s.tick, gridDim.x - 1) == gridDim.x - 1) ? 1u : 0u;
    __syncthreads();
    if (!is_last) return;
    __threadfence();

    __shared__ float a0[HID], c0[HID], a1[HID], c1[HID], red[HID];
    int h = threadIdx.x;
    float sp  = g_s.acc[28];
    float sp2 = g_s.acc[29];
    float sr2 = g_s.acc[30];
    float sr  = (float)NNZt / (float)NE;

    if (h < HID) {
        float sa = 0.f, sc = 0.f;
#pragma unroll
        for (int j = 0; j < DIN; j++) {
            float w = W0[j * HID + h];
            sa += g_s.acc[j] * w;
            sc += g_s.acc[14 + j] * w;
        }
        a0[h] = sa + sp2 * b0[h];
        c0[h] = sc + sr2 * b0[h];
    }
    __syncthreads();
    if (h < HID) {
        float sa = 0.f, sc = 0.f;
        for (int m = 0; m < HID; m++) {
            float w = Wl0[m * HID + h];
            sa += a0[m] * w;
            sc += c0[m] * w;
        }
        a1[h] = sa + sp2 * bl0[h];
        c1[h] = sc + sr2 * bl0[h];
    }
    __syncthreads();
    if (h < HID) {
        float sa = 0.f, sc = 0.f;
        for (int m = 0; m < HID; m++) {
            float w = Wl1[m * HID + h];
            sa += a1[m] * w;
            sc += c1[m] * w;
        }
        float a2h = sa + sp * bl1[h];
        float c2h = sc + sr * bl1[h];
        red[h] = a2h * Wo0[h] + c2h * Wo1[h];
    }
    __syncthreads();
    for (int s = HID / 2; s > 0; s >>= 1) {
        if (h < s) red[h] += red[h + s];
        __syncthreads();
    }
    if (h == 0) out[0] = red[0] + bo0[0] + bo1[0];
}

extern "C" void kernel_launch(void* const* d_in, const int* in_sizes, int n_in,
                              void* d_out, int out_size) {
    const float* x_0  = (const float*)d_in[0];
    const int*   rows = (const int*)d_in[2];
    const int*   cols = (const int*)d_in[3];
    const float* W0   = (const float*)d_in[4];
    const float* b0   = (const float*)d_in[5];
    const float* Wl0  = (const float*)d_in[8];
    const float* bl0  = (const float*)d_in[9];
    const float* Wl1  = (const float*)d_in[10];
    const float* bl1  = (const float*)d_in[11];
    const float* Wo0  = (const float*)d_in[12];
    const float* bo0  = (const float*)d_in[13];
    const float* Wo1  = (const float*)d_in[14];
    const float* bo1  = (const float*)d_in[15];
    float* out = (float*)d_out;

    void* p_s;
    cudaGetSymbolAddress(&p_s, g_s);
    cudaMemsetAsync(p_s, 0, sizeof(Scratch));

    const int T = 256;
    const int gNV = (NV + T - 1) / T;                 // 391

    k_deg  <<<NNZ_GRID, NNZ_BLK>>>(rows);
    k_scat1<<<NNZ_GRID, NNZ_BLK>>>(rows, cols);
    k_gath1<<<NNZ_GRID, NNZ_BLK>>>(rows, cols);
    k_prep <<<gNV, T>>>();
    k_scat2<<<NNZ_GRID, NNZ_BLK>>>(rows, cols);
    k_gath2<<<NNZ_GRID, NNZ_BLK>>>(rows, cols);
    k_reduce_final<<<RED_GRID, RED_BLK>>>(x_0, W0, b0, Wl0, bl0, Wl1, bl1,
                                          Wo0, bo0, Wo1, bo1, out);
}